// round 5
// baseline (speedup 1.0000x reference)
#include <cuda_runtime.h>
#include <cstdint>

// PARAFAC / CP reconstruction: out[a,b,c] = sum_k f0[k,a] * f1[k,b] * f2[k,c]
// A = B = C = 512, RANK = 16, fp32. 536 MB output.
//
// Round-5: replace per-warp STG (LSU outstanding-store limited; DRAM stuck at 58%
// with no pipe saturated) with SMEM-staged TMA BULK STORES:
//   - per block: 64 contiguous 2KB output rows = one contiguous 128 KB region
//   - compute 8 rows -> STS.128 into staging buffer -> elected thread issues
//     cp.async.bulk.global.shared::cta (16 KB), double-buffered
//   - warps do fire-and-forget STS; TMA engine owns global-write concurrency;
//     compute of group g+1 overlaps the bulk store of group g
// Arithmetic identical to round 3 (k-paired f32x2, zero splat movs) -> same rel_err.

#define A_DIM 512
#define B_DIM 512
#define C_DIM 512
#define RANK  16
#define BCHUNK 64
#define GROUP  8          // rows per bulk store (8 x 2KB = 16KB)
#define NGROUPS (BCHUNK / GROUP)
#define NTHREADS 128      // 128 c-lanes x 4 c each = 512 c

typedef unsigned long long ull;

__device__ __forceinline__ ull pack2(float lo, float hi) {
    ull r;
    asm("mov.b64 %0, {%1,%2};" : "=l"(r) : "r"(__float_as_uint(lo)), "r"(__float_as_uint(hi)));
    return r;
}

__device__ __forceinline__ uint32_t smem_u32(const void* p) {
    uint32_t a;
    asm("{ .reg .u64 t; cvta.to.shared.u64 t, %1; cvt.u32.u64 %0, t; }" : "=r"(a) : "l"(p));
    return a;
}

__global__ __launch_bounds__(NTHREADS, 5)
void parafac_kernel(const float* __restrict__ f0,
                    const float* __restrict__ f1,
                    const float* __restrict__ f2,
                    float* __restrict__ out)
{
    // g k-major & contiguous: gsh[j][k] = f0[k][a]*f1[k][b0+j]
    __shared__ __align__(16) float gsh[BCHUNK][RANK];            // 4 KB
    // double-buffered output staging: 2 x 8 rows x 512 floats = 32 KB
    __shared__ __align__(16) float sbuf[2][GROUP][C_DIM];

    const int a  = blockIdx.y;
    const int b0 = blockIdx.x * BCHUNK;
    const int t  = threadIdx.x;
    const int c0 = t * 4;   // thread's fixed c-quad

    // ---- f2 transposed pack (once per block): f2p[p][c] = (f2[2p][c0+c], f2[2p+1][c0+c]) ----
    ull f2p[RANK / 2][4];
#pragma unroll
    for (int p = 0; p < RANK / 2; p++) {
        float4 e = *reinterpret_cast<const float4*>(f2 + (2 * p + 0) * C_DIM + c0);
        float4 o = *reinterpret_cast<const float4*>(f2 + (2 * p + 1) * C_DIM + c0);
        f2p[p][0] = pack2(e.x, o.x);
        f2p[p][1] = pack2(e.y, o.y);
        f2p[p][2] = pack2(e.z, o.z);
        f2p[p][3] = pack2(e.w, o.w);
    }

    // ---- precompute g: 64*16 = 1024 entries, 128 threads -> 8 each ----
#pragma unroll
    for (int i = 0; i < (BCHUNK * RANK) / NTHREADS; i++) {
        int idx = t + i * NTHREADS;
        int j = idx >> 4;     // b offset within chunk
        int k = idx & 15;     // rank index
        gsh[j][k] = f0[k * A_DIM + a] * f1[k * B_DIM + b0 + j];
    }
    __syncthreads();

    float* oblk = out + (size_t)a * (B_DIM * C_DIM) + (size_t)b0 * C_DIM;

    for (int grp = 0; grp < NGROUPS; grp++) {
        const int buf = grp & 1;

        // before overwriting buf, ensure the bulk store that used it (grp-2) is done
        if (grp >= 2) {
            if (t == 0) {
                asm volatile("cp.async.bulk.wait_group 1;" ::: "memory");
            }
            __syncthreads();
        }

#pragma unroll
        for (int jj = 0; jj < GROUP; jj++) {
            const int j = grp * GROUP + jj;

            // 4x LDS.128 (broadcast): 8 pre-packed (g_even, g_odd) pairs
            const ulonglong2* gj = reinterpret_cast<const ulonglong2*>(gsh[j]);
            ulonglong2 u0 = gj[0], u1 = gj[1], u2 = gj[2], u3 = gj[3];
            ull gp[RANK / 2] = { u0.x, u0.y, u1.x, u1.y, u2.x, u2.y, u3.x, u3.y };

            // 4 independent f32x2 accumulator chains; lanes = (even-k, odd-k) partial sums
            ull acc0 = 0ull, acc1 = 0ull, acc2 = 0ull, acc3 = 0ull;
#pragma unroll
            for (int p = 0; p < RANK / 2; p++) {
                asm("fma.rn.f32x2 %0, %1, %2, %0;" : "+l"(acc0) : "l"(f2p[p][0]), "l"(gp[p]));
                asm("fma.rn.f32x2 %0, %1, %2, %0;" : "+l"(acc1) : "l"(f2p[p][1]), "l"(gp[p]));
                asm("fma.rn.f32x2 %0, %1, %2, %0;" : "+l"(acc2) : "l"(f2p[p][2]), "l"(gp[p]));
                asm("fma.rn.f32x2 %0, %1, %2, %0;" : "+l"(acc3) : "l"(f2p[p][3]), "l"(gp[p]));
            }

            float2 h0 = *reinterpret_cast<float2*>(&acc0);
            float2 h1 = *reinterpret_cast<float2*>(&acc1);
            float2 h2 = *reinterpret_cast<float2*>(&acc2);
            float2 h3 = *reinterpret_cast<float2*>(&acc3);
            float4 r = make_float4(h0.x + h0.y, h1.x + h1.y, h2.x + h2.y, h3.x + h3.y);

            // fire-and-forget STS.128 into staging row
            *reinterpret_cast<float4*>(&sbuf[buf][jj][c0]) = r;
        }

        __syncthreads();   // all STS for this group visible

        if (t == 0) {
            uint32_t src = smem_u32(&sbuf[buf][0][0]);
            const float* dst = oblk + (size_t)grp * GROUP * C_DIM;
            asm volatile("fence.proxy.async.shared::cta;" ::: "memory");
            asm volatile("cp.async.bulk.global.shared::cta.bulk_group [%0], [%1], %2;"
                         :: "l"(dst), "r"(src), "n"(GROUP * C_DIM * 4)
                         : "memory");
            asm volatile("cp.async.bulk.commit_group;" ::: "memory");
        }
    }

    // drain all pending bulk stores before block exit
    if (t == 0) {
        asm volatile("cp.async.bulk.wait_group 0;" ::: "memory");
    }
}

extern "C" void kernel_launch(void* const* d_in, const int* in_sizes, int n_in,
                              void* d_out, int out_size)
{
    const float* f0 = (const float*)d_in[0];
    const float* f1 = (const float*)d_in[1];
    const float* f2 = (const float*)d_in[2];
    float* out = (float*)d_out;

    dim3 grid(B_DIM / BCHUNK, A_DIM);   // (8, 512) = 4096 blocks
    dim3 block(NTHREADS);
    parafac_kernel<<<grid, block>>>(f0, f1, f2, out);
}